// round 1
// baseline (speedup 1.0000x reference)
#include <cuda_runtime.h>
#include <cuda_bf16.h>

// Sparsemax over rows: x, mask are [8192, 4096] fp32; out fp32 same shape.
// z = (mask ? x : NEG_BIG) * 2 ; tau solves sum(relu(z - tau)) = 1 (Newton);
// out = relu(z - tau)  (mask multiply is implied: masked z is hugely negative).

#define ROWS 8192
#define COLS 4096
#define THREADS 256
#define NWARPS (THREADS / 32)
#define ELEMS (COLS / THREADS)   // 16 floats per thread
#define VEC (ELEMS / 4)          // 4 float4 per thread

__global__ __launch_bounds__(THREADS, 8)
void sparsemax_kernel(const float* __restrict__ x,
                      const float* __restrict__ m,
                      float* __restrict__ out) {
    const int row = blockIdx.x;
    const int t   = threadIdx.x;
    const int lane = t & 31;
    const int wid  = t >> 5;

    const float4* __restrict__ xr = reinterpret_cast<const float4*>(x + (size_t)row * COLS);
    const float4* __restrict__ mr = reinterpret_cast<const float4*>(m + (size_t)row * COLS);
    float4* __restrict__ orow     = reinterpret_cast<float4*>(out + (size_t)row * COLS);

    __shared__ float sh[2 * NWARPS];

    // ---- Load + compute z, track local max ----
    float z[ELEMS];
    float vmax = -3.0e38f;
    const float NEGZ = -9999999.9f * 2.0f;  // masked value after temperature
#pragma unroll
    for (int v = 0; v < VEC; v++) {
        float4 xv = xr[t + v * THREADS];
        float4 mv = mr[t + v * THREADS];
        float z0 = (mv.x != 0.0f) ? (xv.x * 2.0f) : NEGZ;
        float z1 = (mv.y != 0.0f) ? (xv.y * 2.0f) : NEGZ;
        float z2 = (mv.z != 0.0f) ? (xv.z * 2.0f) : NEGZ;
        float z3 = (mv.w != 0.0f) ? (xv.w * 2.0f) : NEGZ;
        z[v * 4 + 0] = z0;
        z[v * 4 + 1] = z1;
        z[v * 4 + 2] = z2;
        z[v * 4 + 3] = z3;
        vmax = fmaxf(vmax, fmaxf(fmaxf(z0, z1), fmaxf(z2, z3)));
    }

    // ---- Block max reduction ----
#pragma unroll
    for (int o = 16; o > 0; o >>= 1)
        vmax = fmaxf(vmax, __shfl_xor_sync(0xFFFFFFFFu, vmax, o));
    if (lane == 0) sh[wid] = vmax;
    __syncthreads();
    float zmax = -3.0e38f;
#pragma unroll
    for (int i = 0; i < NWARPS; i++) zmax = fmaxf(zmax, sh[i]);
    __syncthreads();

    // ---- Newton iterations on f(T) = sum(relu(z - T)) - 1 ----
    // T0 = zmax - 1 guarantees f(T0) >= 0; Newton from the left is monotone
    // increasing on a convex piecewise-linear f and terminates exactly.
    float T = zmax - 1.0f;
#pragma unroll 1
    for (int it = 0; it < 32; ++it) {
        float s = 0.0f, c = 0.0f;
#pragma unroll
        for (int e = 0; e < ELEMS; e++) {
            float d = z[e] - T;
            if (d > 0.0f) { s += d; c += 1.0f; }
        }
#pragma unroll
        for (int o = 16; o > 0; o >>= 1) {
            s += __shfl_xor_sync(0xFFFFFFFFu, s, o);
            c += __shfl_xor_sync(0xFFFFFFFFu, c, o);
        }
        if (lane == 0) { sh[wid] = s; sh[NWARPS + wid] = c; }
        __syncthreads();
        float S = 0.0f, C = 0.0f;
#pragma unroll
        for (int i = 0; i < NWARPS; i++) { S += sh[i]; C += sh[NWARPS + i]; }
        __syncthreads();

        if (C < 0.5f) break;              // degenerate guard (shouldn't happen)
        float delta = (S - 1.0f) / C;
        T += delta;
        if (fabsf(delta) < 1e-6f) break;  // uniform across block (S,C identical)
    }

    // ---- Output: relu(z - T). Masked entries are ~-2e7, relu -> 0. ----
#pragma unroll
    for (int v = 0; v < VEC; v++) {
        float4 ov;
        ov.x = fmaxf(0.0f, z[v * 4 + 0] - T);
        ov.y = fmaxf(0.0f, z[v * 4 + 1] - T);
        ov.z = fmaxf(0.0f, z[v * 4 + 2] - T);
        ov.w = fmaxf(0.0f, z[v * 4 + 3] - T);
        orow[t + v * THREADS] = ov;
    }
}

extern "C" void kernel_launch(void* const* d_in, const int* in_sizes, int n_in,
                              void* d_out, int out_size) {
    const float* x = (const float*)d_in[0];
    const float* m = (const float*)d_in[1];
    float* out = (float*)d_out;
    sparsemax_kernel<<<ROWS, THREADS>>>(x, m, out);
}

// round 2
// speedup vs baseline: 1.0005x; 1.0005x over previous
#include <cuda_runtime.h>
#include <cuda_bf16.h>

// Sparsemax over rows: x, mask are [8192, 4096] fp32; out fp32 same shape.
// z = (mask ? x : NEG_BIG) * 2 ; tau solves sum(relu(z - tau)) = 1 (Newton);
// out = relu(z - tau)  (mask multiply implied: masked z is hugely negative).
//
// Pure streaming workload (384 MB total, zero reuse) -> use evict-first
// cache hints on all three streams to maximize achieved HBM bandwidth.

#define ROWS 8192
#define COLS 4096
#define THREADS 256
#define NWARPS (THREADS / 32)
#define ELEMS (COLS / THREADS)   // 16 floats per thread
#define VEC (ELEMS / 4)          // 4 float4 per thread

__global__ __launch_bounds__(THREADS, 8)
void sparsemax_kernel(const float* __restrict__ x,
                      const float* __restrict__ m,
                      float* __restrict__ out) {
    const int row = blockIdx.x;
    const int t   = threadIdx.x;
    const int lane = t & 31;
    const int wid  = t >> 5;

    const float4* __restrict__ xr = reinterpret_cast<const float4*>(x + (size_t)row * COLS);
    const float4* __restrict__ mr = reinterpret_cast<const float4*>(m + (size_t)row * COLS);
    float4* __restrict__ orow     = reinterpret_cast<float4*>(out + (size_t)row * COLS);

    __shared__ float sh[2 * NWARPS];

    // ---- Load (streaming / evict-first) + compute z, track local max ----
    float z[ELEMS];
    float vmax = -3.0e38f;
    const float NEGZ = -9999999.9f * 2.0f;  // masked value after temperature
#pragma unroll
    for (int v = 0; v < VEC; v++) {
        float4 xv = __ldcs(&xr[t + v * THREADS]);
        float4 mv = __ldcs(&mr[t + v * THREADS]);
        float z0 = (mv.x != 0.0f) ? (xv.x * 2.0f) : NEGZ;
        float z1 = (mv.y != 0.0f) ? (xv.y * 2.0f) : NEGZ;
        float z2 = (mv.z != 0.0f) ? (xv.z * 2.0f) : NEGZ;
        float z3 = (mv.w != 0.0f) ? (xv.w * 2.0f) : NEGZ;
        z[v * 4 + 0] = z0;
        z[v * 4 + 1] = z1;
        z[v * 4 + 2] = z2;
        z[v * 4 + 3] = z3;
        vmax = fmaxf(vmax, fmaxf(fmaxf(z0, z1), fmaxf(z2, z3)));
    }

    // ---- Block max reduction ----
#pragma unroll
    for (int o = 16; o > 0; o >>= 1)
        vmax = fmaxf(vmax, __shfl_xor_sync(0xFFFFFFFFu, vmax, o));
    if (lane == 0) sh[wid] = vmax;
    __syncthreads();
    float zmax = -3.0e38f;
#pragma unroll
    for (int i = 0; i < NWARPS; i++) zmax = fmaxf(zmax, sh[i]);
    __syncthreads();

    // ---- Newton iterations on f(T) = sum(relu(z - T)) - 1 ----
    // T0 = zmax - 1 guarantees f(T0) >= 0; Newton from the left is monotone
    // increasing on a convex piecewise-linear f and terminates exactly.
    float T = zmax - 1.0f;
#pragma unroll 1
    for (int it = 0; it < 32; ++it) {
        float s = 0.0f, c = 0.0f;
#pragma unroll
        for (int e = 0; e < ELEMS; e++) {
            float d = z[e] - T;
            if (d > 0.0f) { s += d; c += 1.0f; }
        }
#pragma unroll
        for (int o = 16; o > 0; o >>= 1) {
            s += __shfl_xor_sync(0xFFFFFFFFu, s, o);
            c += __shfl_xor_sync(0xFFFFFFFFu, c, o);
        }
        if (lane == 0) { sh[wid] = s; sh[NWARPS + wid] = c; }
        __syncthreads();
        float S = 0.0f, C = 0.0f;
#pragma unroll
        for (int i = 0; i < NWARPS; i++) { S += sh[i]; C += sh[NWARPS + i]; }
        __syncthreads();

        if (C < 0.5f) break;              // degenerate guard (shouldn't happen)
        float delta = (S - 1.0f) / C;
        T += delta;
        if (fabsf(delta) < 1e-6f) break;  // uniform across block (S,C identical)
    }

    // ---- Output: relu(z - T), streaming store. Masked entries -> 0. ----
#pragma unroll
    for (int v = 0; v < VEC; v++) {
        float4 ov;
        ov.x = fmaxf(0.0f, z[v * 4 + 0] - T);
        ov.y = fmaxf(0.0f, z[v * 4 + 1] - T);
        ov.z = fmaxf(0.0f, z[v * 4 + 2] - T);
        ov.w = fmaxf(0.0f, z[v * 4 + 3] - T);
        __stcs(&orow[t + v * THREADS], ov);
    }
}

extern "C" void kernel_launch(void* const* d_in, const int* in_sizes, int n_in,
                              void* d_out, int out_size) {
    const float* x = (const float*)d_in[0];
    const float* m = (const float*)d_in[1];
    float* out = (float*)d_out;
    sparsemax_kernel<<<ROWS, THREADS>>>(x, m, out);
}

// round 3
// speedup vs baseline: 1.0390x; 1.0385x over previous
#include <cuda_runtime.h>
#include <cuda_bf16.h>

// Sparsemax over rows: x, mask are [8192, 4096] fp32; out fp32 same shape.
// z = (mask ? x : NEG_BIG) * 2 ; tau solves sum(relu(z - tau)) = 1 (Newton);
// out = relu(z - tau)  (mask multiply implied: masked z is hugely negative).
//
// R3: default cache policy (streaming hints regressed in R2); all 8 float4
// loads front-batched into registers for high per-thread MLP; occupancy 5.

#define ROWS 8192
#define COLS 4096
#define THREADS 256
#define NWARPS (THREADS / 32)
#define ELEMS (COLS / THREADS)   // 16 floats per thread
#define VEC (ELEMS / 4)          // 4 float4 per thread

__global__ __launch_bounds__(THREADS, 5)
void sparsemax_kernel(const float* __restrict__ x,
                      const float* __restrict__ m,
                      float* __restrict__ out) {
    const int row = blockIdx.x;
    const int t   = threadIdx.x;
    const int lane = t & 31;
    const int wid  = t >> 5;

    const float4* __restrict__ xr = reinterpret_cast<const float4*>(x + (size_t)row * COLS);
    const float4* __restrict__ mr = reinterpret_cast<const float4*>(m + (size_t)row * COLS);
    float4* __restrict__ orow     = reinterpret_cast<float4*>(out + (size_t)row * COLS);

    __shared__ float sh[2 * NWARPS];

    // ---- Front-batch ALL loads (8 x LDG.128 in flight per thread) ----
    float4 xv[VEC];
    float4 mv[VEC];
#pragma unroll
    for (int v = 0; v < VEC; v++) xv[v] = xr[t + v * THREADS];
#pragma unroll
    for (int v = 0; v < VEC; v++) mv[v] = mr[t + v * THREADS];

    // ---- Apply mask + temperature, track local max ----
    float z[ELEMS];
    float vmax = -3.0e38f;
    const float NEGZ = -9999999.9f * 2.0f;  // masked value after temperature
#pragma unroll
    for (int v = 0; v < VEC; v++) {
        float z0 = (mv[v].x != 0.0f) ? (xv[v].x * 2.0f) : NEGZ;
        float z1 = (mv[v].y != 0.0f) ? (xv[v].y * 2.0f) : NEGZ;
        float z2 = (mv[v].z != 0.0f) ? (xv[v].z * 2.0f) : NEGZ;
        float z3 = (mv[v].w != 0.0f) ? (xv[v].w * 2.0f) : NEGZ;
        z[v * 4 + 0] = z0;
        z[v * 4 + 1] = z1;
        z[v * 4 + 2] = z2;
        z[v * 4 + 3] = z3;
        vmax = fmaxf(vmax, fmaxf(fmaxf(z0, z1), fmaxf(z2, z3)));
    }

    // ---- Block max reduction ----
#pragma unroll
    for (int o = 16; o > 0; o >>= 1)
        vmax = fmaxf(vmax, __shfl_xor_sync(0xFFFFFFFFu, vmax, o));
    if (lane == 0) sh[wid] = vmax;
    __syncthreads();
    float zmax = -3.0e38f;
#pragma unroll
    for (int i = 0; i < NWARPS; i++) zmax = fmaxf(zmax, sh[i]);
    __syncthreads();

    // ---- Newton iterations on f(T) = sum(relu(z - T)) - 1 ----
    // T0 = zmax - 1 guarantees f(T0) >= 0; Newton from the left is monotone
    // increasing on a convex piecewise-linear f and terminates exactly.
    float T = zmax - 1.0f;
#pragma unroll 1
    for (int it = 0; it < 32; ++it) {
        float s = 0.0f, c = 0.0f;
#pragma unroll
        for (int e = 0; e < ELEMS; e++) {
            float d = z[e] - T;
            if (d > 0.0f) { s += d; c += 1.0f; }
        }
#pragma unroll
        for (int o = 16; o > 0; o >>= 1) {
            s += __shfl_xor_sync(0xFFFFFFFFu, s, o);
            c += __shfl_xor_sync(0xFFFFFFFFu, c, o);
        }
        if (lane == 0) { sh[wid] = s; sh[NWARPS + wid] = c; }
        __syncthreads();
        float S = 0.0f, C = 0.0f;
#pragma unroll
        for (int i = 0; i < NWARPS; i++) { S += sh[i]; C += sh[NWARPS + i]; }
        __syncthreads();

        if (C < 0.5f) break;              // degenerate guard (shouldn't happen)
        float delta = (S - 1.0f) / C;
        T += delta;
        if (fabsf(delta) < 1e-6f) break;  // uniform across block (S,C identical)
    }

    // ---- Output: relu(z - T). Masked entries are ~-2e7, relu -> 0. ----
#pragma unroll
    for (int v = 0; v < VEC; v++) {
        float4 ov;
        ov.x = fmaxf(0.0f, z[v * 4 + 0] - T);
        ov.y = fmaxf(0.0f, z[v * 4 + 1] - T);
        ov.z = fmaxf(0.0f, z[v * 4 + 2] - T);
        ov.w = fmaxf(0.0f, z[v * 4 + 3] - T);
        orow[t + v * THREADS] = ov;
    }
}

extern "C" void kernel_launch(void* const* d_in, const int* in_sizes, int n_in,
                              void* d_out, int out_size) {
    const float* x = (const float*)d_in[0];
    const float* m = (const float*)d_in[1];
    float* out = (float*)d_out;
    sparsemax_kernel<<<ROWS, THREADS>>>(x, m, out);
}